// round 1
// baseline (speedup 1.0000x reference)
#include <cuda_runtime.h>
#include <cstdint>

// NF4 codebook (bitsandbytes constants, exact fp32)
__constant__ float c_nf4[16] = {
    -1.0f, -0.6961928009986877f, -0.5250730514526367f, -0.39491748809814453f,
    -0.28444138169288635f, -0.18477343022823334f, -0.09105003625154495f, 0.0f,
    0.07958029955625534f, 0.16093020141124725f, 0.24611230194568634f,
    0.33791524171829224f, 0.4407098591327667f, 0.5626170039176941f,
    0.7229568362236023f, 1.0f};

// Global LUT: 2048 cells x {boundary, val_lo, val_hi, pad}
// Cell c (0..1024) covers xn in [c/512 - 1, (c+1)/512 - 1); cells 1025..2047 are
// only reachable via 1-ulp undershoot below xn=-1 (u just below 2.0).
__device__ float4 g_lut[2048];

__global__ void lut_init_kernel() {
    int c = blockIdx.x * blockDim.x + threadIdx.x;
    if (c >= 2048) return;
    float mid[15];
#pragma unroll
    for (int j = 0; j < 15; j++) mid[j] = (c_nf4[j] + c_nf4[j + 1]) * 0.5f;

    // lower edge of this cell in xn-space
    float xlo = (c <= 1024) ? (float)c * (1.0f / 512.0f) - 1.0f : -1.0f;

    // b = #{ mid[j] < xlo }  -> bucket containing the cell's lower edge.
    // For all xn in (and 1-ulp around) this cell:
    //   idx = b + (xn > mid[b])   (exact, since <=1 boundary per cell)
    int b = 0;
#pragma unroll
    for (int j = 0; j < 15; j++) b += (mid[j] < xlo) ? 1 : 0;

    float bnd = 3.0e38f;
#pragma unroll
    for (int j = 0; j < 15; j++)
        if (j == b) bnd = mid[j];
    float v0 = c_nf4[b];
    float v1 = c_nf4[(b < 15) ? (b + 1) : 15];
    g_lut[c] = make_float4(bnd, v0, v1, 0.0f);
}

// One element: xn = x*rinv; u = xn+3 in [2,4); cell = top-10 mantissa bits of u.
// Byte offset into LUT = (bits(u) >> 9) & 0x7FF0  (includes exp LSB as bit 14,
// which maps u==4.0 exactly to entry 1024 and u just-below-2 to entry 2047).
__device__ __forceinline__ float q1(float a, float rinv, float m, uint32_t lutb) {
    float xn = a * rinv;
    float u  = xn + 3.0f;
    uint32_t sa = lutb + ((__float_as_uint(u) >> 9) & 0x7FF0u);
    float bnd, v0, v1, pad;
    asm("ld.shared.v4.f32 {%0,%1,%2,%3}, [%4];"
        : "=f"(bnd), "=f"(v0), "=f"(v1), "=f"(pad) : "r"(sa));
    return ((xn > bnd) ? v1 : v0) * m;
}

__global__ void __launch_bounds__(256) nf4_kernel(const float* __restrict__ x,
                                                  float* __restrict__ out,
                                                  int nblocks) {
    __shared__ float4 s_lut[2048];
#pragma unroll
    for (int i = 0; i < 8; i++)
        s_lut[threadIdx.x + 256 * i] = g_lut[threadIdx.x + 256 * i];
    __syncthreads();

    uint32_t lutb;
    asm("{\n\t.reg .u64 t;\n\tcvta.to.shared.u64 t, %1;\n\tcvt.u32.u64 %0, t;\n\t}"
        : "=r"(lutb) : "l"(s_lut));

    int blk = blockIdx.x * 8 + (threadIdx.x >> 5);
    if (blk >= nblocks) return;
    int lane = threadIdx.x & 31;

    const float4* px = reinterpret_cast<const float4*>(x) + (size_t)blk * 128 + lane;
    float4* po = reinterpret_cast<float4*>(out) + (size_t)blk * 128 + lane;

    float4 d0 = px[0];
    float4 d1 = px[32];
    float4 d2 = px[64];
    float4 d3 = px[96];

    // absmax over this thread's 16 values (FMNMX with |.| modifiers)
    float m0 = fmaxf(fabsf(d0.x), fabsf(d0.y));
    float m1 = fmaxf(fabsf(d0.z), fabsf(d0.w));
    float m2 = fmaxf(fabsf(d1.x), fabsf(d1.y));
    float m3 = fmaxf(fabsf(d1.z), fabsf(d1.w));
    float m4 = fmaxf(fabsf(d2.x), fabsf(d2.y));
    float m5 = fmaxf(fabsf(d2.z), fabsf(d2.w));
    float m6 = fmaxf(fabsf(d3.x), fabsf(d3.y));
    float m7 = fmaxf(fabsf(d3.z), fabsf(d3.w));
    m0 = fmaxf(m0, m1); m2 = fmaxf(m2, m3);
    m4 = fmaxf(m4, m5); m6 = fmaxf(m6, m7);
    m0 = fmaxf(m0, m2); m4 = fmaxf(m4, m6);
    float m = fmaxf(m0, m4);

    // warp reduce: block absmax (512 elems = 1 warp)
#pragma unroll
    for (int s = 16; s > 0; s >>= 1)
        m = fmaxf(m, __shfl_xor_sync(0xFFFFFFFFu, m, s));

    float scale = (m == 0.0f) ? 1.0f : m;
    float rinv = 1.0f / scale;

    d0.x = q1(d0.x, rinv, m, lutb);
    d0.y = q1(d0.y, rinv, m, lutb);
    d0.z = q1(d0.z, rinv, m, lutb);
    d0.w = q1(d0.w, rinv, m, lutb);
    d1.x = q1(d1.x, rinv, m, lutb);
    d1.y = q1(d1.y, rinv, m, lutb);
    d1.z = q1(d1.z, rinv, m, lutb);
    d1.w = q1(d1.w, rinv, m, lutb);
    d2.x = q1(d2.x, rinv, m, lutb);
    d2.y = q1(d2.y, rinv, m, lutb);
    d2.z = q1(d2.z, rinv, m, lutb);
    d2.w = q1(d2.w, rinv, m, lutb);
    d3.x = q1(d3.x, rinv, m, lutb);
    d3.y = q1(d3.y, rinv, m, lutb);
    d3.z = q1(d3.z, rinv, m, lutb);
    d3.w = q1(d3.w, rinv, m, lutb);

    po[0]  = d0;
    po[32] = d1;
    po[64] = d2;
    po[96] = d3;
}

extern "C" void kernel_launch(void* const* d_in, const int* in_sizes, int n_in,
                              void* d_out, int out_size) {
    const float* x = (const float*)d_in[0];
    float* out = (float*)d_out;
    int n = in_sizes[0];
    int nblocks = n / 512;                  // 65536 quant blocks
    lut_init_kernel<<<8, 256>>>();
    int ncta = (nblocks + 7) / 8;           // 8 warps (blocks) per CTA
    nf4_kernel<<<ncta, 256>>>(x, out, nblocks);
}

// round 4
// speedup vs baseline: 1.4267x; 1.4267x over previous
#include <cuda_runtime.h>
#include <cstdint>

// NF4 codebook (bitsandbytes constants, exact fp32)
__constant__ float c_nf4[16] = {
    -1.0f, -0.6961928009986877f, -0.5250730514526367f, -0.39491748809814453f,
    -0.28444138169288635f, -0.18477343022823334f, -0.09105003625154495f, 0.0f,
    0.07958029955625534f, 0.16093020141124725f, 0.24611230194568634f,
    0.33791524171829224f, 0.4407098591327667f, 0.5626170039176941f,
    0.7229568362236023f, 1.0f};

// Global LUT: 2048 cells x {boundary, base_index (as int bits)}
// Cell c (0..1024) covers xn in [c/512 - 1, (c+1)/512 - 1); cells 1025..2047
// are reachable only via 1-ulp undershoot below xn=-1 (u just below 2.0).
// For all xn mapping to cell c:  idx = base + (xn > bnd);  value = cb[idx].
// (v1 = cb[base+1] always, so only base is needed — exact by construction.)
__device__ float2 g_lut[2048];

__global__ void lut_init_kernel() {
    int c = blockIdx.x * blockDim.x + threadIdx.x;
    if (c >= 2048) return;
    float mid[15];
#pragma unroll
    for (int j = 0; j < 15; j++) mid[j] = (c_nf4[j] + c_nf4[j + 1]) * 0.5f;

    // lower edge of this cell in xn-space
    float xlo = (c <= 1024) ? (float)c * (1.0f / 512.0f) - 1.0f : -1.0f;

    // base = #{ mid[j] < xlo }; at most one boundary (mid[base]) inside the cell
    int b = 0;
#pragma unroll
    for (int j = 0; j < 15; j++) b += (mid[j] < xlo) ? 1 : 0;

    float bnd = 3.0e38f;  // no boundary in cell -> compare always false
#pragma unroll
    for (int j = 0; j < 15; j++)
        if (j == b) bnd = mid[j];
    g_lut[c] = make_float2(bnd, __int_as_float(b));
}

// One element. u = xn+3 in [2,4): top-10 mantissa bits of u give a uniform
// 1024-cell grid; exponent LSB (bit 23) extends addressing for the u==4.0
// and u->2^- one-ulp cases. 8-byte entries: off = (bits >> 10) & 0x3FF8.
__device__ __forceinline__ float q1(float a, float rinv, float m, float cbv,
                                    uint32_t lutb) {
    float xn = a * rinv;
    uint32_t bits = __float_as_uint(xn + 3.0f);
    uint32_t sa = lutb + ((bits >> 10) & 0x3FF8u);
    float bnd, basef;
    asm("ld.shared.v2.f32 {%0,%1}, [%2];" : "=f"(bnd), "=f"(basef) : "r"(sa));
    int idx = __float_as_int(basef) + (xn > bnd ? 1 : 0);
    float v = __shfl_sync(0xFFFFFFFFu, cbv, idx);
    return v * m;
}

__global__ void __launch_bounds__(256) nf4_kernel(const float* __restrict__ x,
                                                  float* __restrict__ out,
                                                  int nblocks, int nwarps) {
    __shared__ float2 s_lut[2048];
    {
        float4* d = reinterpret_cast<float4*>(s_lut);
        const float4* s = reinterpret_cast<const float4*>(g_lut);
#pragma unroll
        for (int i = 0; i < 4; i++)
            d[threadIdx.x + 256 * i] = s[threadIdx.x + 256 * i];
    }
    __syncthreads();

    uint32_t lutb;
    asm("{\n\t.reg .u64 t;\n\tcvta.to.shared.u64 t, %1;\n\tcvt.u32.u64 %0, t;\n\t}"
        : "=r"(lutb) : "l"(s_lut));

    int lane = threadIdx.x & 31;
    float cbv = c_nf4[lane & 15];  // register-resident codebook, one value/lane

    int wid = (blockIdx.x * 256 + threadIdx.x) >> 5;

    for (int blk = wid; blk < nblocks; blk += nwarps) {
        const float4* px = reinterpret_cast<const float4*>(x) + (size_t)blk * 128 + lane;
        float4* po = reinterpret_cast<float4*>(out) + (size_t)blk * 128 + lane;

        float4 d0 = __ldcs(px);
        float4 d1 = __ldcs(px + 32);
        float4 d2 = __ldcs(px + 64);
        float4 d3 = __ldcs(px + 96);

        // absmax over this thread's 16 values
        float m0 = fmaxf(fabsf(d0.x), fabsf(d0.y));
        float m1 = fmaxf(fabsf(d0.z), fabsf(d0.w));
        float m2 = fmaxf(fabsf(d1.x), fabsf(d1.y));
        float m3 = fmaxf(fabsf(d1.z), fabsf(d1.w));
        float m4 = fmaxf(fabsf(d2.x), fabsf(d2.y));
        float m5 = fmaxf(fabsf(d2.z), fabsf(d2.w));
        float m6 = fmaxf(fabsf(d3.x), fabsf(d3.y));
        float m7 = fmaxf(fabsf(d3.z), fabsf(d3.w));
        m0 = fmaxf(m0, m1); m2 = fmaxf(m2, m3);
        m4 = fmaxf(m4, m5); m6 = fmaxf(m6, m7);
        m0 = fmaxf(m0, m2); m4 = fmaxf(m4, m6);
        float m = fmaxf(m0, m4);

        // warp reduce: block absmax (512 elems = 1 warp)
#pragma unroll
        for (int s = 16; s > 0; s >>= 1)
            m = fmaxf(m, __shfl_xor_sync(0xFFFFFFFFu, m, s));

        float scale = (m == 0.0f) ? 1.0f : m;
        float rinv = 1.0f / scale;

        d0.x = q1(d0.x, rinv, m, cbv, lutb);
        d0.y = q1(d0.y, rinv, m, cbv, lutb);
        d0.z = q1(d0.z, rinv, m, cbv, lutb);
        d0.w = q1(d0.w, rinv, m, cbv, lutb);
        d1.x = q1(d1.x, rinv, m, cbv, lutb);
        d1.y = q1(d1.y, rinv, m, cbv, lutb);
        d1.z = q1(d1.z, rinv, m, cbv, lutb);
        d1.w = q1(d1.w, rinv, m, cbv, lutb);
        d2.x = q1(d2.x, rinv, m, cbv, lutb);
        d2.y = q1(d2.y, rinv, m, cbv, lutb);
        d2.z = q1(d2.z, rinv, m, cbv, lutb);
        d2.w = q1(d2.w, rinv, m, cbv, lutb);
        d3.x = q1(d3.x, rinv, m, cbv, lutb);
        d3.y = q1(d3.y, rinv, m, cbv, lutb);
        d3.z = q1(d3.z, rinv, m, cbv, lutb);
        d3.w = q1(d3.w, rinv, m, cbv, lutb);

        __stcs(po, d0);
        __stcs(po + 32, d1);
        __stcs(po + 64, d2);
        __stcs(po + 96, d3);
    }
}

extern "C" void kernel_launch(void* const* d_in, const int* in_sizes, int n_in,
                              void* d_out, int out_size) {
    const float* x = (const float*)d_in[0];
    float* out = (float*)d_out;
    int n = in_sizes[0];
    int nblocks = n / 512;  // 65536 quant blocks
    lut_init_kernel<<<8, 256>>>();
    int ncta = 1024;        // persistent-ish: each warp loops over ~8 blocks
    int nwarps = ncta * 8;
    nf4_kernel<<<ncta, 256>>>(x, out, nblocks, nwarps);
}